// round 1
// baseline (speedup 1.0000x reference)
#include <cuda_runtime.h>

#define Hh 2048
#define Ww 2448
#define HWn (Hh * Ww)
#define P4n (HWn / 4)   // 1,253,376 — exactly divisible

// fp32 constants replicating the reference's fp32 arithmetic
#define TWO_PI_F   6.28318530717958648f   // rounds to 6.2831855f
#define PI_HALF_F  1.57079632679489662f
#define PI3_HALF_F 4.71238898038468986f
#define SCALE_F    2.54647908947032537f   // 16/(2*pi)
// sin/cos of the fp32 deltas as XLA computes them (contaminated, not 0/±1)
#define S2C (-8.74227766e-8f)   // sin(pi_f32)
#define C1C (-4.37113883e-8f)   // cos(pi/2_f32)
#define C3C (-1.07284409e-7f)   // cos(fp32(3*2pi_f32)/4)

__device__ __forceinline__ float lane(const float4& v, int l) {
    return l == 0 ? v.x : (l == 1 ? v.y : (l == 2 ? v.z : v.w));
}

// ~2e-6-accurate atan2; fast-math immune (no libcalls except MUFU via __fdividef)
__device__ __forceinline__ float fast_atan2f(float y, float x) {
    float ax = fabsf(x), ay = fabsf(y);
    float mx = fmaxf(ax, ay);
    float mn = fminf(ax, ay);
    float t  = __fdividef(mn, fmaxf(mx, 1.17549435e-38f));  // guard 0/0
    float s  = t * t;
    float p  = -0.01172120f;
    p = fmaf(p, s, 0.05265332f);
    p = fmaf(p, s, -0.11643287f);
    p = fmaf(p, s, 0.19354346f);
    p = fmaf(p, s, -0.33262347f);
    p = fmaf(p, s, 0.99997726f);
    float r = p * t;
    r = (ay > ax)   ? (1.57079632679489662f - r) : r;
    r = (x < 0.0f)  ? (3.14159265358979324f - r) : r;
    r = (y < 0.0f)  ? -r : r;
    return r;
}

__device__ __forceinline__ float unwrap_one(float sv, float cv, unsigned G) {
    // gray -> binary (prefix XOR from MSB)
    unsigned b = G ^ (G >> 1);
    b ^= b >> 2;
    b ^= b >> 4;
    int v2 = (int)b;
    int k1 = v2 >> 1;          // == sum gi[:-1]*ratio[1:]
    int k2 = (v2 + 1) >> 1;    // == (dec_v2 + 1) // 2
    float p = -fast_atan2f(sv, cv);
    if (p < 0.0f) p = __fadd_rn(p, TWO_PI_F);
    float add;
    if (p <= PI_HALF_F)
        add = __fmul_rn(TWO_PI_F, (float)k2);
    else if (p < PI3_HALF_F)
        add = __fmul_rn(TWO_PI_F, (float)k1);
    else
        add = __fadd_rn(__fmul_rn(TWO_PI_F, (float)k2), -TWO_PI_F);
    return __fadd_rn(p, add);
}

__global__ void __launch_bounds__(256)
cgc_kernel(const float4* __restrict__ in4, float4* __restrict__ out4) {
    int t = blockIdx.x * blockDim.x + threadIdx.x;
    if (t >= P4n) return;

    // 8 phase-shift planes
    float4 a0 = in4[0 * P4n + t];
    float4 a1 = in4[1 * P4n + t];
    float4 a2 = in4[2 * P4n + t];
    float4 a3 = in4[3 * P4n + t];
    float4 a4 = in4[4 * P4n + t];
    float4 a5 = in4[5 * P4n + t];
    float4 a6 = in4[6 * P4n + t];
    float4 a7 = in4[7 * P4n + t];

    float thr[4], sc[4], cc[4], sr[4], cr[4];
    bool  mask[4];
    const float Tq = __int_as_float(0x3C23D70B);  // preimage of bg>0.05 under 0.5*sqrt

    #pragma unroll
    for (int l = 0; l < 4; l++) {
        float i0 = lane(a0, l), i1 = lane(a1, l), i2 = lane(a2, l), i3 = lane(a3, l);
        float i4 = lane(a4, l), i5 = lane(a5, l), i6 = lane(a6, l), i7 = lane(a7, l);

        // threshold = mean, sequential add order, no fma
        float s = i0;
        s = __fadd_rn(s, i1); s = __fadd_rn(s, i2); s = __fadd_rn(s, i3);
        s = __fadd_rn(s, i4); s = __fadd_rn(s, i5); s = __fadd_rn(s, i6);
        s = __fadd_rn(s, i7);
        thr[l] = __fmul_rn(s, 0.125f);

        // einsum with XLA's contaminated sin/cos coefficients, mul-then-add order
        sc[l] = __fadd_rn(__fadd_rn(i1, __fmul_rn(S2C, i2)), -i3);
        cc[l] = __fadd_rn(__fadd_rn(__fadd_rn(i0, __fmul_rn(C1C, i1)), -i2),
                          __fmul_rn(C3C, i3));
        sr[l] = __fadd_rn(__fadd_rn(i5, __fmul_rn(S2C, i6)), -i7);
        cr[l] = __fadd_rn(__fadd_rn(__fadd_rn(i4, __fmul_rn(C1C, i5)), -i6),
                          __fmul_rn(C3C, i7));

        float qc = __fadd_rn(__fmul_rn(sc[l], sc[l]), __fmul_rn(cc[l], cc[l]));
        float qr = __fadd_rn(__fmul_rn(sr[l], sr[l]), __fmul_rn(cr[l], cr[l]));
        mask[l] = (qc > Tq) || (qr > Tq);
    }

    // graycode planes: col = 8..15, row = 16..23
    unsigned Gc[4] = {0u, 0u, 0u, 0u};
    #pragma unroll
    for (int k = 0; k < 8; k++) {
        float4 g = in4[(8 + k) * P4n + t];
        #pragma unroll
        for (int l = 0; l < 4; l++)
            Gc[l] = (Gc[l] << 1) | (lane(g, l) > thr[l] ? 1u : 0u);
    }
    unsigned Gr[4] = {0u, 0u, 0u, 0u};
    #pragma unroll
    for (int k = 0; k < 8; k++) {
        float4 g = in4[(16 + k) * P4n + t];
        #pragma unroll
        for (int l = 0; l < 4; l++)
            Gr[l] = (Gr[l] << 1) | (lane(g, l) > thr[l] ? 1u : 0u);
    }

    float colv[4], rowv[4];
    #pragma unroll
    for (int l = 0; l < 4; l++) {
        float pc = unwrap_one(sc[l], cc[l], Gc[l]);
        float pr = unwrap_one(sr[l], cr[l], Gr[l]);
        float m  = mask[l] ? 1.0f : 0.0f;
        colv[l] = __fmul_rn(__fmul_rn(pc, m), SCALE_F);
        rowv[l] = __fmul_rn(__fmul_rn(pr, m), SCALE_F);
    }

    // output [H, W, 2] interleaved: 8 floats per thread = 2 float4 stores
    out4[2 * t + 0] = make_float4(colv[0], rowv[0], colv[1], rowv[1]);
    out4[2 * t + 1] = make_float4(colv[2], rowv[2], colv[3], rowv[3]);
}

extern "C" void kernel_launch(void* const* d_in, const int* in_sizes, int n_in,
                              void* d_out, int out_size) {
    (void)in_sizes; (void)n_in; (void)out_size;
    const float4* in4  = (const float4*)d_in[0];
    float4*       out4 = (float4*)d_out;
    int blocks = (P4n + 255) / 256;   // 4896, exact
    cgc_kernel<<<blocks, 256>>>(in4, out4);
}

// round 2
// speedup vs baseline: 1.1121x; 1.1121x over previous
#include <cuda_runtime.h>

#define Hh 2048
#define Ww 2448
#define HWn (Hh * Ww)    // 5,013,504

// fp32 constants replicating the reference's fp32 arithmetic
#define TWO_PI_F   6.28318530717958648f
#define PI_HALF_F  1.57079632679489662f
#define PI3_HALF_F 4.71238898038468986f
#define SCALE_F    2.54647908947032537f   // 16/(2*pi)
// sin/cos of the fp32 deltas as XLA computes them (contaminated, not 0/±1)
#define S2C (-8.74227766e-8f)   // sin(pi_f32)
#define C1C (-4.37113883e-8f)   // cos(pi/2_f32)
#define C3C (-1.07284409e-7f)   // cos(fp32(3*2pi_f32)/4)

// ~2e-6-accurate atan2; fast-math immune (no libcalls except MUFU via __fdividef)
__device__ __forceinline__ float fast_atan2f(float y, float x) {
    float ax = fabsf(x), ay = fabsf(y);
    float mx = fmaxf(ax, ay);
    float mn = fminf(ax, ay);
    float t  = __fdividef(mn, fmaxf(mx, 1.17549435e-38f));  // guard 0/0
    float s  = t * t;
    float p  = -0.01172120f;
    p = fmaf(p, s, 0.05265332f);
    p = fmaf(p, s, -0.11643287f);
    p = fmaf(p, s, 0.19354346f);
    p = fmaf(p, s, -0.33262347f);
    p = fmaf(p, s, 0.99997726f);
    float r = p * t;
    r = (ay > ax)   ? (1.57079632679489662f - r) : r;
    r = (x < 0.0f)  ? (3.14159265358979324f - r) : r;
    r = (y < 0.0f)  ? -r : r;
    return r;
}

__device__ __forceinline__ float unwrap_one(float sv, float cv, unsigned G) {
    // gray -> binary (prefix XOR from MSB)
    unsigned b = G ^ (G >> 1);
    b ^= b >> 2;
    b ^= b >> 4;
    int v2 = (int)b;
    int k1 = v2 >> 1;          // == sum gi[:-1]*ratio[1:]
    int k2 = (v2 + 1) >> 1;    // == (dec_v2 + 1) // 2
    float p = -fast_atan2f(sv, cv);
    if (p < 0.0f) p = __fadd_rn(p, TWO_PI_F);
    float add;
    if (p <= PI_HALF_F)
        add = __fmul_rn(TWO_PI_F, (float)k2);
    else if (p < PI3_HALF_F)
        add = __fmul_rn(TWO_PI_F, (float)k1);
    else
        add = __fadd_rn(__fmul_rn(TWO_PI_F, (float)k2), -TWO_PI_F);
    return __fadd_rn(p, add);
}

__global__ void __launch_bounds__(256, 4)
cgc_kernel(const float* __restrict__ in, float2* __restrict__ out) {
    int t = blockIdx.x * 256 + threadIdx.x;   // one pixel per thread; grid exact

    // Issue ALL 24 plane loads up front — maximal MLP, no consumer in between.
    float v[24];
    #pragma unroll
    for (int k = 0; k < 24; k++)
        v[k] = __ldcs(in + (size_t)k * HWn + t);

    float i0 = v[0], i1 = v[1], i2 = v[2], i3 = v[3];
    float i4 = v[4], i5 = v[5], i6 = v[6], i7 = v[7];

    // threshold = mean, sequential add order, no fma
    float s = i0;
    s = __fadd_rn(s, i1); s = __fadd_rn(s, i2); s = __fadd_rn(s, i3);
    s = __fadd_rn(s, i4); s = __fadd_rn(s, i5); s = __fadd_rn(s, i6);
    s = __fadd_rn(s, i7);
    float thr = __fmul_rn(s, 0.125f);

    // einsum with XLA's contaminated sin/cos coefficients, mul-then-add order
    float sc = __fadd_rn(__fadd_rn(i1, __fmul_rn(S2C, i2)), -i3);
    float cc = __fadd_rn(__fadd_rn(__fadd_rn(i0, __fmul_rn(C1C, i1)), -i2),
                         __fmul_rn(C3C, i3));
    float sr = __fadd_rn(__fadd_rn(i5, __fmul_rn(S2C, i6)), -i7);
    float cr = __fadd_rn(__fadd_rn(__fadd_rn(i4, __fmul_rn(C1C, i5)), -i6),
                         __fmul_rn(C3C, i7));

    // mask: 0.5*sqrt(q) > 0.05  <=>  q > succ(0.01f) (exact preimage, sqrt-free)
    const float Tq = __int_as_float(0x3C23D70B);
    float qc = __fadd_rn(__fmul_rn(sc, sc), __fmul_rn(cc, cc));
    float qr = __fadd_rn(__fmul_rn(sr, sr), __fmul_rn(cr, cr));
    float m  = ((qc > Tq) || (qr > Tq)) ? 1.0f : 0.0f;

    // graycode planes: col = 8..15, row = 16..23 (MSB first)
    unsigned Gc = 0u, Gr = 0u;
    #pragma unroll
    for (int k = 0; k < 8; k++)
        Gc = (Gc << 1) | (v[8 + k] > thr ? 1u : 0u);
    #pragma unroll
    for (int k = 0; k < 8; k++)
        Gr = (Gr << 1) | (v[16 + k] > thr ? 1u : 0u);

    float pc = unwrap_one(sc, cc, Gc);
    float pr = unwrap_one(sr, cr, Gr);
    float colv = __fmul_rn(__fmul_rn(pc, m), SCALE_F);
    float rowv = __fmul_rn(__fmul_rn(pr, m), SCALE_F);

    out[t] = make_float2(colv, rowv);   // [H, W, 2] interleaved, coalesced 8B
}

extern "C" void kernel_launch(void* const* d_in, const int* in_sizes, int n_in,
                              void* d_out, int out_size) {
    (void)in_sizes; (void)n_in; (void)out_size;
    const float* in  = (const float*)d_in[0];
    float2*      out = (float2*)d_out;
    int blocks = HWn / 256;   // 19584, exact
    cgc_kernel<<<blocks, 256>>>(in, out);
}